// round 14
// baseline (speedup 1.0000x reference)
#include <cuda_runtime.h>
#include <math.h>

#define NSENT 2048
#define BB    64

__device__ float g_pre [(size_t)NSENT * 64 * 768];
__device__ float g_sent[NSENT * 256];
__device__ float g_dpre[NSENT * 1536];
__device__ float g_doc [BB * 512];
__device__ float g_hid [BB * 256];
__device__ int   g_order_s[NSENT];
__device__ int   g_order_d[BB];

#define SMEM_K1   (3 * 64 * 132 * 4)                    // 101376: B + 2 A bufs
#define SMEM_K2   ((256*132 + 128*132 + 3*16*132) * 4)  // 228096
#define SMEM_GEMM ((64*129 + 128*64) * 4)
#define SMEM_K4   ((32768 + 1536) * 4)                  // 137216
#define SMEM_K6   ((16384 + 1280) * 4)

// packed f32x2 fma (SASS FFMA2)
__device__ __forceinline__ void ffma2(unsigned long long& d,
                                      unsigned long long a,
                                      unsigned long long b) {
    asm("fma.rn.f32x2 %0, %1, %2, %0;" : "+l"(d) : "l"(a), "l"(b));
}
__device__ __forceinline__ float f2sum(unsigned long long v) {
    return __uint_as_float((unsigned)v) + __uint_as_float((unsigned)(v >> 32));
}
__device__ __forceinline__ unsigned tf32r(float x) {
    unsigned u; asm("cvt.rna.tf32.f32 %0, %1;" : "=r"(u) : "f"(x)); return u;
}
__device__ __forceinline__ void mma8(float c[4], const unsigned a[4], const unsigned b[2]) {
    asm("mma.sync.aligned.m16n8k8.row.col.f32.tf32.tf32.f32 "
        "{%0,%1,%2,%3},{%4,%5,%6,%7},{%8,%9},{%0,%1,%2,%3};"
        : "+f"(c[0]), "+f"(c[1]), "+f"(c[2]), "+f"(c[3])
        : "r"(a[0]), "r"(a[1]), "r"(a[2]), "r"(a[3]), "r"(b[0]), "r"(b[1]));
}
__device__ __forceinline__ unsigned smem_u32(const void* p) {
    return (unsigned)__cvta_generic_to_shared(p);
}
__device__ __forceinline__ void mbar_wait(unsigned mbar, unsigned phase) {
    asm volatile(
        "{\n\t.reg .pred P;\n\t"
        "LW%=:\n\t"
        "mbarrier.try_wait.parity.shared::cta.b64 P, [%0], %1, 0x989680;\n\t"
        "@P bra LD%=;\n\t"
        "bra LW%=;\n\t"
        "LD%=:\n\t}"
        :: "r"(mbar), "r"(phase) : "memory");
}
__device__ __forceinline__ void bulk_issue(unsigned dst, const void* src,
                                           unsigned bytes, unsigned mbar) {
    asm volatile("mbarrier.arrive.expect_tx.shared.b64 _, [%0], %1;"
                 :: "r"(mbar), "r"(bytes) : "memory");
    asm volatile(
        "cp.async.bulk.shared::cluster.global.mbarrier::complete_tx::bytes "
        "[%0], [%1], %2, [%3];"
        :: "r"(dst), "l"(src), "r"(bytes), "r"(mbar) : "memory");
}

// ---------------- K0: counting sorts ----------------
__global__ void k0_sort(const int* __restrict__ L, const int* __restrict__ L2)
{
    int tid = threadIdx.x;
    if (blockIdx.x == 0) {
        __shared__ int lens[NSENT];
        __shared__ int cnt[64];
        for (int i = tid; i < NSENT; i += 256) lens[i] = L[i];
        if (tid < 64) cnt[tid] = 0;
        __syncthreads();
        for (int i = tid; i < NSENT; i += 256) atomicAdd(&cnt[lens[i]], 1);
        __syncthreads();
        if (tid < 64) {
            int o = 0;
            for (int u = 0; u < tid; u++) o += cnt[u];
            for (int i = 0; i < NSENT; i++)
                if (lens[i] == tid) g_order_s[o++] = i;
        }
    } else {
        __shared__ int l2s[BB];
        __shared__ int cnt2[32];
        if (tid < BB) l2s[tid] = L2[tid];
        if (tid < 32) cnt2[tid] = 0;
        __syncthreads();
        if (tid < BB) atomicAdd(&cnt2[l2s[tid]], 1);
        __syncthreads();
        if (tid < 32) {
            int o = 0;
            for (int u = 0; u < tid; u++) o += cnt2[u];
            for (int i = 0; i < BB; i++)
                if (l2s[i] == tid) g_order_d[o++] = i;
        }
    }
}

// ---------------- K1: x-projection GEMM, 8 sentences/block, FFMA2 -----------
__global__ void __launch_bounds__(256) k1_wordgemm(
    const int* __restrict__ X, const int* __restrict__ L,
    const float* __restrict__ emb,
    const float* __restrict__ sWg_f, const float* __restrict__ sbg_f,
    const float* __restrict__ sWc_f, const float* __restrict__ sbc_f,
    const float* __restrict__ sWg_b, const float* __restrict__ sbg_b,
    const float* __restrict__ sWc_b, const float* __restrict__ sbc_b)
{
    extern __shared__ float sm[];
    float* BshT = sm;                 // [64 cols][132 k]
    float* Ab0  = sm + 64 * 132;      // [64 rows][132 k]
    float* Ab1  = sm + 2 * 64 * 132;

    int sgrp = blockIdx.x;            // sentences sgrp*8 .. +7
    int col0 = blockIdx.y * 64;
    const float* src; const float* bias; int ldN, cofs;
    if (col0 < 256)      { src = sWg_f; bias = sbg_f; ldN = 256; cofs = col0;       }
    else if (col0 < 384) { src = sWc_f; bias = sbc_f; ldN = 128; cofs = col0 - 256; }
    else if (col0 < 640) { src = sWg_b; bias = sbg_b; ldN = 256; cofs = col0 - 384; }
    else                 { src = sWc_b; bias = sbc_b; ldN = 128; cofs = col0 - 640; }

    int tid = threadIdx.x;

    // B transposed load (once per block)
    {
        int c = tid & 63;
        const float* colp = src + cofs + c;
#pragma unroll
        for (int kq = (tid >> 6) * 4; kq < 128; kq += 16) {
            float4 v;
            v.x = __ldg(colp + (kq + 0) * ldN);
            v.y = __ldg(colp + (kq + 1) * ldN);
            v.z = __ldg(colp + (kq + 2) * ldN);
            v.w = __ldg(colp + (kq + 3) * ldN);
            *(float4*)(BshT + c * 132 + kq) = v;
        }
    }

    int r0    = (tid >> 4) * 4;
    int cbase = tid & 15;
    float bvv[4];
#pragma unroll
    for (int c = 0; c < 4; c++) bvv[c] = __ldg(bias + cofs + cbase + c * 16);

    // preload sentence 0
    int s0 = sgrp * 8;
    int curlen = L[s0];
    {
#pragma unroll
        for (int i = 0; i < 8; i++) {
            int f = tid + i * 256;
            int row = f >> 5, c4 = f & 31;
            if (row < curlen) {
                int wid = X[s0 * 64 + row];
                float4 v = __ldg((const float4*)(emb + (size_t)wid * 128) + c4);
                *(float4*)(Ab0 + row * 132 + c4 * 4) = v;
            }
        }
    }
    __syncthreads();

    for (int it = 0; it < 8; it++) {
        int s = sgrp * 8 + it;
        float* Acur = (it & 1) ? Ab1 : Ab0;
        float* Anxt = (it & 1) ? Ab0 : Ab1;

        int nlen = 0;
        if (it < 7) {
            nlen = L[s + 1];
            // prefetch next sentence (LDGs batched; STS after)
            float4 pv[8];
            int prow[8];
#pragma unroll
            for (int i = 0; i < 8; i++) {
                int f = tid + i * 256;
                int row = f >> 5, c4 = f & 31;
                prow[i] = -1;
                if (row < nlen) {
                    int wid = X[(s + 1) * 64 + row];
                    pv[i] = __ldg((const float4*)(emb + (size_t)wid * 128) + c4);
                    prow[i] = row * 132 + c4 * 4;
                }
            }
#pragma unroll
            for (int i = 0; i < 8; i++)
                if (prow[i] >= 0) *(float4*)(Anxt + prow[i]) = pv[i];
        }

        if (r0 < curlen) {
            unsigned long long acc2[4][4];
#pragma unroll
            for (int q = 0; q < 4; q++)
#pragma unroll
                for (int c = 0; c < 4; c++) acc2[q][c] = 0ull;

#pragma unroll 4
            for (int k = 0; k < 128; k += 4) {
                ulonglong2 a[4], b[4];
#pragma unroll
                for (int q = 0; q < 4; q++)
                    a[q] = *(const ulonglong2*)(Acur + (r0 + q) * 132 + k);
#pragma unroll
                for (int c = 0; c < 4; c++)
                    b[c] = *(const ulonglong2*)(BshT + (cbase + c * 16) * 132 + k);
#pragma unroll
                for (int q = 0; q < 4; q++)
#pragma unroll
                    for (int c = 0; c < 4; c++) {
                        ffma2(acc2[q][c], a[q].x, b[c].x);
                        ffma2(acc2[q][c], a[q].y, b[c].y);
                    }
            }

#pragma unroll
            for (int q = 0; q < 4; q++) {
                if (r0 + q < curlen) {
                    float* op = g_pre + ((size_t)s * 64 + r0 + q) * 768 + col0;
#pragma unroll
                    for (int c = 0; c < 4; c++)
                        op[cbase + c * 16] = f2sum(acc2[q][c]) + bvv[c];
                }
            }
        }
        __syncthreads();
        curlen = nlen;
    }
}

// ---------------- K2: sentence bi-GRU, tf32 MMA recurrence (stride 132) -----
__global__ void __launch_bounds__(512) k2_sentgru(
    const int* __restrict__ L,
    const float* __restrict__ sWg_f, const float* __restrict__ sWc_f,
    const float* __restrict__ sWg_b, const float* __restrict__ sWc_b)
{
    extern __shared__ float sm[];
    unsigned* WgTu = (unsigned*)sm;            // [256 j][132 k]
    unsigned* WcTu = WgTu + 256 * 132;         // [128 j][132 k]
    float* hS  = (float*)(WcTu + 128 * 132);   // [16][132]
    float* rhS = hS  + 16 * 132;
    float* uS  = rhS + 16 * 132;
    __shared__ int slen[16], sid[16], smax;

    int dir = blockIdx.x & 1;
    int grp = 127 - (blockIdx.x >> 1);
    int tid = threadIdx.x;

    const float* wgsrc = (dir ? sWg_b : sWg_f) + 128 * 256;
    const float* wcsrc = (dir ? sWc_b : sWc_f) + 128 * 128;

    {
        int j = tid & 255;
        const float* colp = wgsrc + j;
#pragma unroll
        for (int kq = (tid >> 8) * 4; kq < 128; kq += 8) {
            WgTu[j * 132 + kq + 0] = tf32r(__ldg(colp + (kq + 0) * 256));
            WgTu[j * 132 + kq + 1] = tf32r(__ldg(colp + (kq + 1) * 256));
            WgTu[j * 132 + kq + 2] = tf32r(__ldg(colp + (kq + 2) * 256));
            WgTu[j * 132 + kq + 3] = tf32r(__ldg(colp + (kq + 3) * 256));
        }
    }
    {
        int j = tid & 127;
        const float* colp = wcsrc + j;
#pragma unroll
        for (int kq = (tid >> 7) * 4; kq < 128; kq += 16) {
            WcTu[j * 132 + kq + 0] = tf32r(__ldg(colp + (kq + 0) * 128));
            WcTu[j * 132 + kq + 1] = tf32r(__ldg(colp + (kq + 1) * 128));
            WcTu[j * 132 + kq + 2] = tf32r(__ldg(colp + (kq + 2) * 128));
            WcTu[j * 132 + kq + 3] = tf32r(__ldg(colp + (kq + 3) * 128));
        }
    }
    if (tid < 16) {
        int ss = g_order_s[grp * 16 + tid];
        sid[tid]  = ss;
        slen[tid] = L[ss];
    }
    for (int i = tid; i < 16 * 132; i += 512) hS[i] = 0.f;
    __syncthreads();
    if (tid == 0) {
        int m = 0;
        for (int i = 0; i < 16; i++) m = max(m, slen[i]);
        smax = m;
    }
    __syncthreads();
    int maxlen = smax;

    int wrp = tid >> 5, lane = tid & 31;
    int g = lane >> 2, tig = lane & 3;
    int jbase = wrp * 16;
    int jc0   = wrp * 8;
    int gbase = dir ? 384 : 0;
    int cbase = dir ? 640 : 256;

    for (int t = 0; t < maxlen; t++) {
        float c0[4] = {0,0,0,0}, c1[4] = {0,0,0,0};
#pragma unroll
        for (int k = 0; k < 128; k += 8) {
            unsigned a[4], b0[2], b1[2];
            a[0] = tf32r(hS[g * 132 + k + tig]);
            a[1] = tf32r(hS[(g + 8) * 132 + k + tig]);
            a[2] = tf32r(hS[g * 132 + k + 4 + tig]);
            a[3] = tf32r(hS[(g + 8) * 132 + k + 4 + tig]);
            b0[0] = WgTu[(jbase + g) * 132 + k + tig];
            b0[1] = WgTu[(jbase + g) * 132 + k + 4 + tig];
            b1[0] = WgTu[(jbase + 8 + g) * 132 + k + tig];
            b1[1] = WgTu[(jbase + 8 + g) * 132 + k + 4 + tig];
            mma8(c0, a, b0);
            mma8(c1, a, b1);
        }
#pragma unroll
        for (int tl = 0; tl < 2; tl++) {
            float* cc = tl ? c1 : c0;
#pragma unroll
            for (int e = 0; e < 4; e++) {
                int r = (e < 2) ? g : g + 8;
                int j = jbase + tl * 8 + 2 * tig + (e & 1);
                int len = slen[r];
                bool valid = t < len;
                float gg = 0.f;
                if (valid) {
                    int widx = dir ? (len - 1 - t) : t;
                    float p = __ldg(g_pre + ((size_t)sid[r] * 64 + widx) * 768 + gbase + j);
                    gg = 1.f / (1.f + __expf(-(cc[e] + p)));
                }
                if (j < 128) rhS[r * 132 + j]       = valid ? gg * hS[r * 132 + j] : 0.f;
                else         uS [r * 132 + j - 128] = valid ? gg : 1.f;
            }
        }
        __syncthreads();

        float cc[4] = {0,0,0,0};
#pragma unroll
        for (int k = 0; k < 128; k += 8) {
            unsigned a[4], b[2];
            a[0] = tf32r(rhS[g * 132 + k + tig]);
            a[1] = tf32r(rhS[(g + 8) * 132 + k + tig]);
            a[2] = tf32r(rhS[g * 132 + k + 4 + tig]);
            a[3] = tf32r(rhS[(g + 8) * 132 + k + 4 + tig]);
            b[0] = WcTu[(jc0 + g) * 132 + k + tig];
            b[1] = WcTu[(jc0 + g) * 132 + k + 4 + tig];
            mma8(cc, a, b);
        }
#pragma unroll
        for (int e = 0; e < 4; e++) {
            int r = (e < 2) ? g : g + 8;
            int jc = jc0 + 2 * tig + (e & 1);
            int len = slen[r];
            if (t < len) {
                int widx = dir ? (len - 1 - t) : t;
                float p = __ldg(g_pre + ((size_t)sid[r] * 64 + widx) * 768 + cbase + jc);
                float c = tanhf(cc[e] + p);
                float u = uS[r * 132 + jc];
                hS[r * 132 + jc] = u * hS[r * 132 + jc] + (1.f - u) * c;
            }
        }
        __syncthreads();
    }

#pragma unroll
    for (int e = 0; e < 4; e++) {
        int r = (e < 2) ? g : g + 8;
        int jc = jc0 + 2 * tig + (e & 1);
        g_sent[sid[r] * 256 + dir * 128 + jc] = hS[r * 132 + jc];
    }
}

// ---------------- K3: doc x-projection GEMM ----------------
__global__ void __launch_bounds__(256) k3_docgemm(
    const float* __restrict__ dWg_f, const float* __restrict__ dbg_f,
    const float* __restrict__ dWc_f, const float* __restrict__ dbc_f,
    const float* __restrict__ dWg_b, const float* __restrict__ dbg_b,
    const float* __restrict__ dWc_b, const float* __restrict__ dbc_b)
{
    extern __shared__ float sm[];
    float* Ash = sm;
    float* Bsh = sm + 64 * 129;

    int rb   = blockIdx.x;
    int col0 = blockIdx.y * 64;
    const float* src; const float* bias; int ldN, cofs;
    if (col0 < 512)       { src = dWg_f; bias = dbg_f; ldN = 512; cofs = col0;        }
    else if (col0 < 768)  { src = dWc_f; bias = dbc_f; ldN = 256; cofs = col0 - 512;  }
    else if (col0 < 1280) { src = dWg_b; bias = dbg_b; ldN = 512; cofs = col0 - 768;  }
    else                  { src = dWc_b; bias = dbc_b; ldN = 256; cofs = col0 - 1280; }

    int tid = threadIdx.x;
    int r0 = (tid >> 4) * 4;
    int c0 = (tid & 15) * 4;
    float acc[4][4];
#pragma unroll
    for (int q = 0; q < 4; q++)
#pragma unroll
        for (int c = 0; c < 4; c++) acc[q][c] = 0.f;

    for (int ch = 0; ch < 2; ch++) {
#pragma unroll
        for (int i = 0; i < 8; i++) {
            int f = tid + i * 256;
            int row = f >> 5, c4 = f & 31;
            float4 v = *(const float4*)(g_sent + (rb * 64 + row) * 256 + ch * 128 + c4 * 4);
            Ash[row * 129 + c4 * 4 + 0] = v.x;
            Ash[row * 129 + c4 * 4 + 1] = v.y;
            Ash[row * 129 + c4 * 4 + 2] = v.z;
            Ash[row * 129 + c4 * 4 + 3] = v.w;
        }
#pragma unroll
        for (int i = 0; i < 8; i++) {
            int f = tid + i * 256;
            int k = f >> 4, c4 = f & 15;
            float4 v = __ldg((const float4*)(src + (ch * 128 + k) * ldN + cofs) + c4);
            *(float4*)(Bsh + k * 64 + c4 * 4) = v;
        }
        __syncthreads();
#pragma unroll 8
        for (int k = 0; k < 128; k++) {
            float a0 = Ash[(r0 + 0) * 129 + k];
            float a1 = Ash[(r0 + 1) * 129 + k];
            float a2 = Ash[(r0 + 2) * 129 + k];
            float a3 = Ash[(r0 + 3) * 129 + k];
            float4 b = *(float4*)(Bsh + k * 64 + c0);
            acc[0][0] += a0 * b.x; acc[0][1] += a0 * b.y; acc[0][2] += a0 * b.z; acc[0][3] += a0 * b.w;
            acc[1][0] += a1 * b.x; acc[1][1] += a1 * b.y; acc[1][2] += a1 * b.z; acc[1][3] += a1 * b.w;
            acc[2][0] += a2 * b.x; acc[2][1] += a2 * b.y; acc[2][2] += a2 * b.z; acc[2][3] += a2 * b.w;
            acc[3][0] += a3 * b.x; acc[3][1] += a3 * b.y; acc[3][2] += a3 * b.z; acc[3][3] += a3 * b.w;
        }
        __syncthreads();
    }

    float4 bv = *(const float4*)(bias + cofs + c0);
#pragma unroll
    for (int q = 0; q < 4; q++) {
        float4 o;
        o.x = acc[q][0] + bv.x; o.y = acc[q][1] + bv.y;
        o.z = acc[q][2] + bv.z; o.w = acc[q][3] + bv.w;
        *(float4*)(g_dpre + (size_t)(rb * 64 + r0 + q) * 1536 + col0 + c0) = o;
    }
}

// ---------------- K4: doc bi-GRU, 2 docs/block, bulk-streamed weights -------
__global__ void __launch_bounds__(512) k4_docgru(
    const float* __restrict__ dWg_f, const float* __restrict__ dWc_f,
    const float* __restrict__ dWg_b, const float* __restrict__ dWc_b,
    const int* __restrict__ L2)
{
    extern __shared__ float sm[];
    float* buf0 = sm;
    float* buf1 = sm + 16384;
    float* hst  = sm + 32768;
    float* rhst = hst + 512;
    float* ust  = rhst + 512;
    __shared__ unsigned long long mbar[2];
    __shared__ int docid[2], dlen[2];

    int dir = blockIdx.x & 1;
    int grp = 31 - (blockIdx.x >> 1);
    int tid = threadIdx.x;

    const float* WgH = (dir ? dWg_b : dWg_f) + 256 * 512;
    const float* WcH = (dir ? dWc_b : dWc_f) + 256 * 256;

    if (tid < 2) {
        int dd = g_order_d[grp * 2 + tid];
        docid[tid] = dd;
        dlen[tid] = L2[dd];
    }
    hst[tid] = 0.f;
    if (tid == 0) {
        asm volatile("mbarrier.init.shared.b64 [%0], 1;" :: "r"(smem_u32(&mbar[0])) : "memory");
        asm volatile("mbarrier.init.shared.b64 [%0], 1;" :: "r"(smem_u32(&mbar[1])) : "memory");
        asm volatile("fence.proxy.async;" ::: "memory");
    }
    __syncthreads();

    int maxlen = max(dlen[0], dlen[1]);
    int ntiles = maxlen * 16;
    unsigned mb0 = smem_u32(&mbar[0]), mb1 = smem_u32(&mbar[1]);
    unsigned ba0 = smem_u32(buf0),     ba1 = smem_u32(buf1);

    auto issue_tile = [&](int tt) {
        if (tt >= ntiles) return;
        int w = tt & 15;
        unsigned dst = (tt & 1) ? ba1 : ba0;
        unsigned mb  = (tt & 1) ? mb1 : mb0;
        if (w < 8) bulk_issue(dst, WgH + w * (32 * 512), 32 * 512 * 4, mb);
        else       bulk_issue(dst, WcH + (w - 8) * (32 * 256), 32 * 256 * 4, mb);
    };

    if (tid == 0) { issue_tile(0); issue_tile(1); }

    int gofs = dir ? 768 : 0;
    int cofs = dir ? 1280 : 512;
    int j = tid;
    int tc = 0;

    for (int t = 0; t < maxlen; t++) {
        float a0 = 0.f, a1 = 0.f;
        for (int w = 0; w < 8; w++, tc++) {
            const float* wb = (tc & 1) ? buf1 : buf0;
            mbar_wait((tc & 1) ? mb1 : mb0, (tc >> 1) & 1);
            int k0 = w * 32;
#pragma unroll
            for (int k4 = 0; k4 < 8; k4++) {
                float w0 = wb[(k4 * 4 + 0) * 512 + j];
                float w1 = wb[(k4 * 4 + 1) * 512 + j];
                float w2 = wb[(k4 * 4 + 2) * 512 + j];
                float w3 = wb[(k4 * 4 + 3) * 512 + j];
                float4 h0 = *(const float4*)(hst + k0 + k4 * 4);
                float4 h1 = *(const float4*)(hst + 256 + k0 + k4 * 4);
                a0 += h0.x * w0 + h0.y * w1 + h0.z * w2 + h0.w * w3;
                a1 += h1.x * w0 + h1.y * w1 + h1.z * w2 + h1.w * w3;
            }
            __syncthreads();
            if (tid == 0) issue_tile(tc + 2);
        }
#pragma unroll
        for (int d = 0; d < 2; d++) {
            float acc = d ? a1 : a0;
            int len = dlen[d];
            bool valid = t < len;
            float g = 0.f;
            if (valid) {
                int widx = dir ? (len - 1 - t) : t;
                float p = g_dpre[(docid[d] * 32 + widx) * 1536 + gofs + j];
                g = 1.f / (1.f + __expf(-(acc + p)));
            }
            if (j < 256) rhst[d * 256 + j]         = valid ? g * hst[d * 256 + j] : 0.f;
            else         ust [d * 256 + (j - 256)] = valid ? g : 1.f;
        }
        __syncthreads();

        float c0a = 0.f, c1a = 0.f;
        for (int w = 0; w < 8; w++, tc++) {
            const float* wb = (tc & 1) ? buf1 : buf0;
            mbar_wait((tc & 1) ? mb1 : mb0, (tc >> 1) & 1);
            if (tid < 256) {
                int k0 = w * 32;
#pragma unroll
                for (int k4 = 0; k4 < 8; k4++) {
                    float w0 = wb[(k4 * 4 + 0) * 256 + tid];
                    float w1 = wb[(k4 * 4 + 1) * 256 + tid];
                    float w2 = wb[(k4 * 4 + 2) * 256 + tid];
                    float w3 = wb[(k4 * 4 + 3) * 256 + tid];
                    float4 r0 = *(const float4*)(rhst + k0 + k4 * 4);
                    float4 r1 = *(const float4*)(rhst + 256 + k0 + k4 * 4);
                    c0a += r0.x * w0 + r0.y * w1 + r0.z * w2 + r0.w * w3;
                    c1a += r1.x * w0 + r1.y * w1 + r1.z * w2 + r1.w * w3;
                }
            }
            __syncthreads();
            if (tid == 0) issue_tile(tc + 2);
        }
        if (tid < 256) {
#pragma unroll
            for (int d = 0; d < 2; d++) {
                int len = dlen[d];
                if (t < len) {
                    int widx = dir ? (len - 1 - t) : t;
                    float p = g_dpre[(docid[d] * 32 + widx) * 1536 + cofs + tid];
                    float c = tanhf((d ? c1a : c0a) + p);
                    float uu = ust[d * 256 + tid];
                    hst[d * 256 + tid] = uu * hst[d * 256 + tid] + (1.f - uu) * c;
                }
            }
        }
        __syncthreads();
    }

    {
        int d = tid >> 8, jc = tid & 255;
        g_doc[docid[d] * 512 + dir * 256 + jc] = hst[d * 256 + jc];
    }
}

// ---------------- K5: MLP hidden GEMM + relu ----------------
__global__ void __launch_bounds__(256) k5_mlp1(
    const float* __restrict__ W1, const float* __restrict__ b1)
{
    extern __shared__ float sm[];
    float* Ash = sm;
    float* Bsh = sm + 64 * 129;
    int col0 = blockIdx.x * 64;
    int tid = threadIdx.x;
    int r0 = (tid >> 4) * 4, c0 = (tid & 15) * 4;
    float acc[4][4];
#pragma unroll
    for (int q = 0; q < 4; q++)
#pragma unroll
        for (int c = 0; c < 4; c++) acc[q][c] = 0.f;

    for (int ch = 0; ch < 4; ch++) {
#pragma unroll
        for (int i = 0; i < 8; i++) {
            int f = tid + i * 256;
            int row = f >> 5, c4 = f & 31;
            float4 v = *(const float4*)(g_doc + row * 512 + ch * 128 + c4 * 4);
            Ash[row * 129 + c4 * 4 + 0] = v.x;
            Ash[row * 129 + c4 * 4 + 1] = v.y;
            Ash[row * 129 + c4 * 4 + 2] = v.z;
            Ash[row * 129 + c4 * 4 + 3] = v.w;
        }
#pragma unroll
        for (int i = 0; i < 8; i++) {
            int f = tid + i * 256;
            int k = f >> 4, c4 = f & 15;
            float4 v = __ldg((const float4*)(W1 + (ch * 128 + k) * 256 + col0) + c4);
            *(float4*)(Bsh + k * 64 + c4 * 4) = v;
        }
        __syncthreads();
#pragma unroll 8
        for (int k = 0; k < 128; k++) {
            float a0 = Ash[(r0 + 0) * 129 + k];
            float a1 = Ash[(r0 + 1) * 129 + k];
            float a2 = Ash[(r0 + 2) * 129 + k];
            float a3 = Ash[(r0 + 3) * 129 + k];
            float4 b = *(float4*)(Bsh + k * 64 + c0);
            acc[0][0] += a0 * b.x; acc[0][1] += a0 * b.y; acc[0][2] += a0 * b.z; acc[0][3] += a0 * b.w;
            acc[1][0] += a1 * b.x; acc[1][1] += a1 * b.y; acc[1][2] += a1 * b.z; acc[1][3] += a1 * b.w;
            acc[2][0] += a2 * b.x; acc[2][1] += a2 * b.y; acc[2][2] += a2 * b.z; acc[2][3] += a2 * b.w;
            acc[3][0] += a3 * b.x; acc[3][1] += a3 * b.y; acc[3][2] += a3 * b.z; acc[3][3] += a3 * b.w;
        }
        __syncthreads();
    }

    float4 bv = *(const float4*)(b1 + col0 + c0);
#pragma unroll
    for (int q = 0; q < 4; q++) {
        float4 o;
        o.x = fmaxf(acc[q][0] + bv.x, 0.f); o.y = fmaxf(acc[q][1] + bv.y, 0.f);
        o.z = fmaxf(acc[q][2] + bv.z, 0.f); o.w = fmaxf(acc[q][3] + bv.w, 0.f);
        *(float4*)(g_hid + (r0 + q) * 256 + col0 + c0) = o;
    }
}

// ---------------- K6: logits ----------------
__global__ void __launch_bounds__(512) k6_logits(
    const float* __restrict__ W2, const float* __restrict__ b2,
    float* __restrict__ out)
{
    extern __shared__ float sm[];
    float* hidS = sm;
    float* W2s  = sm + 16384;
    int tid = threadIdx.x;
    for (int i = tid; i < 16384; i += 512) hidS[i] = g_hid[i];
    for (int i = tid; i < 1280; i += 512) W2s[i] = W2[i];
    __syncthreads();
    if (tid < 320) {
        int doc = tid / 5, o = tid % 5;
        float acc = b2[o];
#pragma unroll 8
        for (int k = 0; k < 256; k++)
            acc += hidS[doc * 256 + k] * W2s[k * 5 + o];
        out[doc * 5 + o] = acc;
    }
}

// ---------------- launcher ----------------
extern "C" void kernel_launch(void* const* d_in, const int* in_sizes, int n_in,
                              void* d_out, int out_size)
{
    const int*   X     = (const int*)d_in[0];
    const int*   L     = (const int*)d_in[1];
    const int*   L2    = (const int*)d_in[2];
    const float* emb   = (const float*)d_in[3];
    const float* sWg_f = (const float*)d_in[4];
    const float* sbg_f = (const float*)d_in[5];
    const float* sWc_f = (const float*)d_in[6];
    const float* sbc_f = (const float*)d_in[7];
    const float* sWg_b = (const float*)d_in[8];
    const float* sbg_b = (const float*)d_in[9];
    const float* sWc_b = (const float*)d_in[10];
    const float* sbc_b = (const float*)d_in[11];
    const float* dWg_f = (const float*)d_in[12];
    const float* dbg_f = (const float*)d_in[13];
    const float* dWc_f = (const float*)d_in[14];
    const float* dbc_f = (const float*)d_in[15];
    const float* dWg_b = (const float*)d_in[16];
    const float* dbg_b = (const float*)d_in[17];
    const float* dWc_b = (const float*)d_in[18];
    const float* dbc_b = (const float*)d_in[19];
    const float* W1    = (const float*)d_in[20];
    const float* b1    = (const float*)d_in[21];
    const float* W2    = (const float*)d_in[22];
    const float* b2    = (const float*)d_in[23];
    float* out = (float*)d_out;

    cudaFuncSetAttribute(k1_wordgemm, cudaFuncAttributeMaxDynamicSharedMemorySize, SMEM_K1);
    cudaFuncSetAttribute(k2_sentgru,  cudaFuncAttributeMaxDynamicSharedMemorySize, SMEM_K2);
    cudaFuncSetAttribute(k3_docgemm,  cudaFuncAttributeMaxDynamicSharedMemorySize, SMEM_GEMM);
    cudaFuncSetAttribute(k4_docgru,   cudaFuncAttributeMaxDynamicSharedMemorySize, SMEM_K4);
    cudaFuncSetAttribute(k5_mlp1,     cudaFuncAttributeMaxDynamicSharedMemorySize, SMEM_GEMM);
    cudaFuncSetAttribute(k6_logits,   cudaFuncAttributeMaxDynamicSharedMemorySize, SMEM_K6);

    k0_sort<<<2, 256>>>(L, L2);
    dim3 g1(256, 12);
    k1_wordgemm<<<g1, 256, SMEM_K1>>>(X, L, emb, sWg_f, sbg_f, sWc_f, sbc_f,
                                      sWg_b, sbg_b, sWc_b, sbc_b);
    k2_sentgru<<<256, 512, SMEM_K2>>>(L, sWg_f, sWc_f, sWg_b, sWc_b);
    dim3 g3(32, 24);
    k3_docgemm<<<g3, 256, SMEM_GEMM>>>(dWg_f, dbg_f, dWc_f, dbc_f,
                                       dWg_b, dbg_b, dWc_b, dbc_b);
    k4_docgru<<<64, 512, SMEM_K4>>>(dWg_f, dWc_f, dWg_b, dWc_b, L2);
    k5_mlp1<<<4, 256, SMEM_GEMM>>>(W1, b1);
    k6_logits<<<1, 512, SMEM_K6>>>(W2, b2, out);
}

// round 15
// speedup vs baseline: 1.0220x; 1.0220x over previous
#include <cuda_runtime.h>
#include <math.h>

#define NSENT 2048
#define BB    64

__device__ float g_pre [(size_t)NSENT * 64 * 768];
__device__ float g_sent[NSENT * 256];
__device__ float g_dpre[NSENT * 1536];
__device__ float g_doc [BB * 512];
__device__ float g_hid [BB * 256];
__device__ int   g_order_s[NSENT];
__device__ int   g_order_d[BB];

#define SMEM_K1   (2 * 64 * 132 * 4)                    // 67584
#define SMEM_K2   ((256*132 + 128*132 + 3*16*132) * 4)  // 228096
#define SMEM_GEMM ((64*129 + 128*64) * 4)
#define SMEM_K4   ((32768 + 1536) * 4)                  // 137216
#define SMEM_K6   ((16384 + 1280) * 4)

// packed f32x2 fma (SASS FFMA2)
__device__ __forceinline__ void ffma2(unsigned long long& d,
                                      unsigned long long a,
                                      unsigned long long b) {
    asm("fma.rn.f32x2 %0, %1, %2, %0;" : "+l"(d) : "l"(a), "l"(b));
}
__device__ __forceinline__ float f2sum(unsigned long long v) {
    return __uint_as_float((unsigned)v) + __uint_as_float((unsigned)(v >> 32));
}
__device__ __forceinline__ unsigned tf32r(float x) {
    unsigned u; asm("cvt.rna.tf32.f32 %0, %1;" : "=r"(u) : "f"(x)); return u;
}
__device__ __forceinline__ void mma8(float c[4], const unsigned a[4], const unsigned b[2]) {
    asm("mma.sync.aligned.m16n8k8.row.col.f32.tf32.tf32.f32 "
        "{%0,%1,%2,%3},{%4,%5,%6,%7},{%8,%9},{%0,%1,%2,%3};"
        : "+f"(c[0]), "+f"(c[1]), "+f"(c[2]), "+f"(c[3])
        : "r"(a[0]), "r"(a[1]), "r"(a[2]), "r"(a[3]), "r"(b[0]), "r"(b[1]));
}
__device__ __forceinline__ unsigned smem_u32(const void* p) {
    return (unsigned)__cvta_generic_to_shared(p);
}
__device__ __forceinline__ void mbar_wait(unsigned mbar, unsigned phase) {
    asm volatile(
        "{\n\t.reg .pred P;\n\t"
        "LW%=:\n\t"
        "mbarrier.try_wait.parity.shared::cta.b64 P, [%0], %1, 0x989680;\n\t"
        "@P bra LD%=;\n\t"
        "bra LW%=;\n\t"
        "LD%=:\n\t}"
        :: "r"(mbar), "r"(phase) : "memory");
}
__device__ __forceinline__ void bulk_issue(unsigned dst, const void* src,
                                           unsigned bytes, unsigned mbar) {
    asm volatile("mbarrier.arrive.expect_tx.shared.b64 _, [%0], %1;"
                 :: "r"(mbar), "r"(bytes) : "memory");
    asm volatile(
        "cp.async.bulk.shared::cluster.global.mbarrier::complete_tx::bytes "
        "[%0], [%1], %2, [%3];"
        :: "r"(dst), "l"(src), "r"(bytes), "r"(mbar) : "memory");
}

// ---------------- K0a: sentence counting sort ----------------
__global__ void k0a_sort(const int* __restrict__ L)
{
    int tid = threadIdx.x;
    __shared__ int lens[NSENT];
    __shared__ int cnt[64];
    for (int i = tid; i < NSENT; i += 256) lens[i] = L[i];
    if (tid < 64) cnt[tid] = 0;
    __syncthreads();
    for (int i = tid; i < NSENT; i += 256) atomicAdd(&cnt[lens[i]], 1);
    __syncthreads();
    if (tid < 64) {
        int o = 0;
        for (int u = 0; u < tid; u++) o += cnt[u];
        for (int i = 0; i < NSENT; i++)
            if (lens[i] == tid) g_order_s[o++] = i;
    }
}

// ---------------- K0b: doc counting sort ----------------
__global__ void k0b_sort(const int* __restrict__ L2)
{
    int tid = threadIdx.x;
    __shared__ int l2s[BB];
    __shared__ int cnt2[32];
    if (tid < BB) l2s[tid] = L2[tid];
    if (tid < 32) cnt2[tid] = 0;
    __syncthreads();
    if (tid < BB) atomicAdd(&cnt2[l2s[tid]], 1);
    __syncthreads();
    if (tid < 32) {
        int o = 0;
        for (int u = 0; u < tid; u++) o += cnt2[u];
        for (int i = 0; i < BB; i++)
            if (l2s[i] == tid) g_order_d[o++] = i;
    }
}

// ---------------- K1: word embed + x-projection GEMM (FFMA2) ----------------
__global__ void __launch_bounds__(256) k1_wordgemm(
    const int* __restrict__ X, const int* __restrict__ L,
    const float* __restrict__ emb,
    const float* __restrict__ sWg_f, const float* __restrict__ sbg_f,
    const float* __restrict__ sWc_f, const float* __restrict__ sbc_f,
    const float* __restrict__ sWg_b, const float* __restrict__ sbg_b,
    const float* __restrict__ sWc_b, const float* __restrict__ sbc_b)
{
    extern __shared__ float sm[];
    float* Ash  = sm;               // [64][132]
    float* BshT = sm + 64 * 132;    // [64 cols][132 k]

    int s    = blockIdx.x;
    int col0 = blockIdx.y * 64;
    int len  = L[s];
    const float* src; const float* bias; int ldN, cofs;
    if (col0 < 256)      { src = sWg_f; bias = sbg_f; ldN = 256; cofs = col0;       }
    else if (col0 < 384) { src = sWc_f; bias = sbc_f; ldN = 128; cofs = col0 - 256; }
    else if (col0 < 640) { src = sWg_b; bias = sbg_b; ldN = 256; cofs = col0 - 384; }
    else                 { src = sWc_b; bias = sbc_b; ldN = 128; cofs = col0 - 640; }

    int tid = threadIdx.x;
#pragma unroll
    for (int i = 0; i < 8; i++) {
        int f = tid + i * 256;
        int row = f >> 5, c4 = f & 31;
        if (row < len) {
            int wid = X[s * 64 + row];
            float4 v = __ldg((const float4*)(emb + (size_t)wid * 128) + c4);
            *(float4*)(Ash + row * 132 + c4 * 4) = v;
        }
    }
    {
        int c = tid & 63;
        const float* colp = src + cofs + c;
#pragma unroll
        for (int kq = (tid >> 6) * 4; kq < 128; kq += 16) {
            float4 v;
            v.x = __ldg(colp + (kq + 0) * ldN);
            v.y = __ldg(colp + (kq + 1) * ldN);
            v.z = __ldg(colp + (kq + 2) * ldN);
            v.w = __ldg(colp + (kq + 3) * ldN);
            *(float4*)(BshT + c * 132 + kq) = v;
        }
    }
    __syncthreads();

    int r0    = (tid >> 4) * 4;
    int cbase = tid & 15;
    if (r0 >= len) return;

    unsigned long long acc2[4][4];
#pragma unroll
    for (int q = 0; q < 4; q++)
#pragma unroll
        for (int c = 0; c < 4; c++) acc2[q][c] = 0ull;

#pragma unroll 4
    for (int k = 0; k < 128; k += 4) {
        ulonglong2 a[4], b[4];
#pragma unroll
        for (int q = 0; q < 4; q++)
            a[q] = *(const ulonglong2*)(Ash + (r0 + q) * 132 + k);
#pragma unroll
        for (int c = 0; c < 4; c++)
            b[c] = *(const ulonglong2*)(BshT + (cbase + c * 16) * 132 + k);
#pragma unroll
        for (int q = 0; q < 4; q++)
#pragma unroll
            for (int c = 0; c < 4; c++) {
                ffma2(acc2[q][c], a[q].x, b[c].x);
                ffma2(acc2[q][c], a[q].y, b[c].y);
            }
    }

#pragma unroll
    for (int q = 0; q < 4; q++) {
        if (r0 + q < len) {
            float* op = g_pre + ((size_t)s * 64 + r0 + q) * 768 + col0;
#pragma unroll
            for (int c = 0; c < 4; c++) {
                int cl = cbase + c * 16;
                op[cl] = f2sum(acc2[q][c]) + __ldg(bias + cofs + cl);
            }
        }
    }
}

// ---------------- K2: sentence bi-GRU, tf32 MMA recurrence (stride 132) -----
__global__ void __launch_bounds__(512) k2_sentgru(
    const int* __restrict__ L,
    const float* __restrict__ sWg_f, const float* __restrict__ sWc_f,
    const float* __restrict__ sWg_b, const float* __restrict__ sWc_b)
{
    extern __shared__ float sm[];
    unsigned* WgTu = (unsigned*)sm;            // [256 j][132 k]
    unsigned* WcTu = WgTu + 256 * 132;         // [128 j][132 k]
    float* hS  = (float*)(WcTu + 128 * 132);   // [16][132]
    float* rhS = hS  + 16 * 132;
    float* uS  = rhS + 16 * 132;
    __shared__ int slen[16], sid[16], smax;

    int dir = blockIdx.x & 1;
    int grp = 127 - (blockIdx.x >> 1);
    int tid = threadIdx.x;

    const float* wgsrc = (dir ? sWg_b : sWg_f) + 128 * 256;
    const float* wcsrc = (dir ? sWc_b : sWc_f) + 128 * 128;

    {
        int j = tid & 255;
        const float* colp = wgsrc + j;
#pragma unroll
        for (int kq = (tid >> 8) * 4; kq < 128; kq += 8) {
            WgTu[j * 132 + kq + 0] = tf32r(__ldg(colp + (kq + 0) * 256));
            WgTu[j * 132 + kq + 1] = tf32r(__ldg(colp + (kq + 1) * 256));
            WgTu[j * 132 + kq + 2] = tf32r(__ldg(colp + (kq + 2) * 256));
            WgTu[j * 132 + kq + 3] = tf32r(__ldg(colp + (kq + 3) * 256));
        }
    }
    {
        int j = tid & 127;
        const float* colp = wcsrc + j;
#pragma unroll
        for (int kq = (tid >> 7) * 4; kq < 128; kq += 16) {
            WcTu[j * 132 + kq + 0] = tf32r(__ldg(colp + (kq + 0) * 128));
            WcTu[j * 132 + kq + 1] = tf32r(__ldg(colp + (kq + 1) * 128));
            WcTu[j * 132 + kq + 2] = tf32r(__ldg(colp + (kq + 2) * 128));
            WcTu[j * 132 + kq + 3] = tf32r(__ldg(colp + (kq + 3) * 128));
        }
    }
    if (tid < 16) {
        int ss = g_order_s[grp * 16 + tid];
        sid[tid]  = ss;
        slen[tid] = L[ss];
    }
    for (int i = tid; i < 16 * 132; i += 512) hS[i] = 0.f;
    __syncthreads();
    if (tid == 0) {
        int m = 0;
        for (int i = 0; i < 16; i++) m = max(m, slen[i]);
        smax = m;
    }
    __syncthreads();
    int maxlen = smax;

    int wrp = tid >> 5, lane = tid & 31;
    int g = lane >> 2, tig = lane & 3;
    int jbase = wrp * 16;
    int jc0   = wrp * 8;
    int gbase = dir ? 384 : 0;
    int cbase = dir ? 640 : 256;

    for (int t = 0; t < maxlen; t++) {
        float c0[4] = {0,0,0,0}, c1[4] = {0,0,0,0};
#pragma unroll
        for (int k = 0; k < 128; k += 8) {
            unsigned a[4], b0[2], b1[2];
            a[0] = tf32r(hS[g * 132 + k + tig]);
            a[1] = tf32r(hS[(g + 8) * 132 + k + tig]);
            a[2] = tf32r(hS[g * 132 + k + 4 + tig]);
            a[3] = tf32r(hS[(g + 8) * 132 + k + 4 + tig]);
            b0[0] = WgTu[(jbase + g) * 132 + k + tig];
            b0[1] = WgTu[(jbase + g) * 132 + k + 4 + tig];
            b1[0] = WgTu[(jbase + 8 + g) * 132 + k + tig];
            b1[1] = WgTu[(jbase + 8 + g) * 132 + k + 4 + tig];
            mma8(c0, a, b0);
            mma8(c1, a, b1);
        }
#pragma unroll
        for (int tl = 0; tl < 2; tl++) {
            float* cc = tl ? c1 : c0;
#pragma unroll
            for (int e = 0; e < 4; e++) {
                int r = (e < 2) ? g : g + 8;
                int j = jbase + tl * 8 + 2 * tig + (e & 1);
                int len = slen[r];
                bool valid = t < len;
                float gg = 0.f;
                if (valid) {
                    int widx = dir ? (len - 1 - t) : t;
                    float p = __ldg(g_pre + ((size_t)sid[r] * 64 + widx) * 768 + gbase + j);
                    gg = 1.f / (1.f + __expf(-(cc[e] + p)));
                }
                if (j < 128) rhS[r * 132 + j]       = valid ? gg * hS[r * 132 + j] : 0.f;
                else         uS [r * 132 + j - 128] = valid ? gg : 1.f;
            }
        }
        __syncthreads();

        float cc[4] = {0,0,0,0};
#pragma unroll
        for (int k = 0; k < 128; k += 8) {
            unsigned a[4], b[2];
            a[0] = tf32r(rhS[g * 132 + k + tig]);
            a[1] = tf32r(rhS[(g + 8) * 132 + k + tig]);
            a[2] = tf32r(rhS[g * 132 + k + 4 + tig]);
            a[3] = tf32r(rhS[(g + 8) * 132 + k + 4 + tig]);
            b[0] = WcTu[(jc0 + g) * 132 + k + tig];
            b[1] = WcTu[(jc0 + g) * 132 + k + 4 + tig];
            mma8(cc, a, b);
        }
#pragma unroll
        for (int e = 0; e < 4; e++) {
            int r = (e < 2) ? g : g + 8;
            int jc = jc0 + 2 * tig + (e & 1);
            int len = slen[r];
            if (t < len) {
                int widx = dir ? (len - 1 - t) : t;
                float p = __ldg(g_pre + ((size_t)sid[r] * 64 + widx) * 768 + cbase + jc);
                float c = tanhf(cc[e] + p);
                float u = uS[r * 132 + jc];
                hS[r * 132 + jc] = u * hS[r * 132 + jc] + (1.f - u) * c;
            }
        }
        __syncthreads();
    }

#pragma unroll
    for (int e = 0; e < 4; e++) {
        int r = (e < 2) ? g : g + 8;
        int jc = jc0 + 2 * tig + (e & 1);
        g_sent[sid[r] * 256 + dir * 128 + jc] = hS[r * 132 + jc];
    }
}

// ---------------- K3: doc x-projection GEMM ----------------
__global__ void __launch_bounds__(256) k3_docgemm(
    const float* __restrict__ dWg_f, const float* __restrict__ dbg_f,
    const float* __restrict__ dWc_f, const float* __restrict__ dbc_f,
    const float* __restrict__ dWg_b, const float* __restrict__ dbg_b,
    const float* __restrict__ dWc_b, const float* __restrict__ dbc_b)
{
    extern __shared__ float sm[];
    float* Ash = sm;
    float* Bsh = sm + 64 * 129;

    int rb   = blockIdx.x;
    int col0 = blockIdx.y * 64;
    const float* src; const float* bias; int ldN, cofs;
    if (col0 < 512)       { src = dWg_f; bias = dbg_f; ldN = 512; cofs = col0;        }
    else if (col0 < 768)  { src = dWc_f; bias = dbc_f; ldN = 256; cofs = col0 - 512;  }
    else if (col0 < 1280) { src = dWg_b; bias = dbg_b; ldN = 512; cofs = col0 - 768;  }
    else                  { src = dWc_b; bias = dbc_b; ldN = 256; cofs = col0 - 1280; }

    int tid = threadIdx.x;
    int r0 = (tid >> 4) * 4;
    int c0 = (tid & 15) * 4;
    float acc[4][4];
#pragma unroll
    for (int q = 0; q < 4; q++)
#pragma unroll
        for (int c = 0; c < 4; c++) acc[q][c] = 0.f;

    for (int ch = 0; ch < 2; ch++) {
#pragma unroll
        for (int i = 0; i < 8; i++) {
            int f = tid + i * 256;
            int row = f >> 5, c4 = f & 31;
            float4 v = *(const float4*)(g_sent + (rb * 64 + row) * 256 + ch * 128 + c4 * 4);
            Ash[row * 129 + c4 * 4 + 0] = v.x;
            Ash[row * 129 + c4 * 4 + 1] = v.y;
            Ash[row * 129 + c4 * 4 + 2] = v.z;
            Ash[row * 129 + c4 * 4 + 3] = v.w;
        }
#pragma unroll
        for (int i = 0; i < 8; i++) {
            int f = tid + i * 256;
            int k = f >> 4, c4 = f & 15;
            float4 v = __ldg((const float4*)(src + (ch * 128 + k) * ldN + cofs) + c4);
            *(float4*)(Bsh + k * 64 + c4 * 4) = v;
        }
        __syncthreads();
#pragma unroll 8
        for (int k = 0; k < 128; k++) {
            float a0 = Ash[(r0 + 0) * 129 + k];
            float a1 = Ash[(r0 + 1) * 129 + k];
            float a2 = Ash[(r0 + 2) * 129 + k];
            float a3 = Ash[(r0 + 3) * 129 + k];
            float4 b = *(float4*)(Bsh + k * 64 + c0);
            acc[0][0] += a0 * b.x; acc[0][1] += a0 * b.y; acc[0][2] += a0 * b.z; acc[0][3] += a0 * b.w;
            acc[1][0] += a1 * b.x; acc[1][1] += a1 * b.y; acc[1][2] += a1 * b.z; acc[1][3] += a1 * b.w;
            acc[2][0] += a2 * b.x; acc[2][1] += a2 * b.y; acc[2][2] += a2 * b.z; acc[2][3] += a2 * b.w;
            acc[3][0] += a3 * b.x; acc[3][1] += a3 * b.y; acc[3][2] += a3 * b.z; acc[3][3] += a3 * b.w;
        }
        __syncthreads();
    }

    float4 bv = *(const float4*)(bias + cofs + c0);
#pragma unroll
    for (int q = 0; q < 4; q++) {
        float4 o;
        o.x = acc[q][0] + bv.x; o.y = acc[q][1] + bv.y;
        o.z = acc[q][2] + bv.z; o.w = acc[q][3] + bv.w;
        *(float4*)(g_dpre + (size_t)(rb * 64 + r0 + q) * 1536 + col0 + c0) = o;
    }
}

// ---------------- K4: doc bi-GRU, 2 docs/block, bulk-streamed weights -------
__global__ void __launch_bounds__(512) k4_docgru(
    const float* __restrict__ dWg_f, const float* __restrict__ dWc_f,
    const float* __restrict__ dWg_b, const float* __restrict__ dWc_b,
    const int* __restrict__ L2)
{
    extern __shared__ float sm[];
    float* buf0 = sm;
    float* buf1 = sm + 16384;
    float* hst  = sm + 32768;
    float* rhst = hst + 512;
    float* ust  = rhst + 512;
    __shared__ unsigned long long mbar[2];
    __shared__ int docid[2], dlen[2];

    int dir = blockIdx.x & 1;
    int grp = 31 - (blockIdx.x >> 1);
    int tid = threadIdx.x;

    const float* WgH = (dir ? dWg_b : dWg_f) + 256 * 512;
    const float* WcH = (dir ? dWc_b : dWc_f) + 256 * 256;

    if (tid < 2) {
        int dd = g_order_d[grp * 2 + tid];
        docid[tid] = dd;
        dlen[tid] = L2[dd];
    }
    hst[tid] = 0.f;
    if (tid == 0) {
        asm volatile("mbarrier.init.shared.b64 [%0], 1;" :: "r"(smem_u32(&mbar[0])) : "memory");
        asm volatile("mbarrier.init.shared.b64 [%0], 1;" :: "r"(smem_u32(&mbar[1])) : "memory");
        asm volatile("fence.proxy.async;" ::: "memory");
    }
    __syncthreads();

    int maxlen = max(dlen[0], dlen[1]);
    int ntiles = maxlen * 16;
    unsigned mb0 = smem_u32(&mbar[0]), mb1 = smem_u32(&mbar[1]);
    unsigned ba0 = smem_u32(buf0),     ba1 = smem_u32(buf1);

    auto issue_tile = [&](int tt) {
        if (tt >= ntiles) return;
        int w = tt & 15;
        unsigned dst = (tt & 1) ? ba1 : ba0;
        unsigned mb  = (tt & 1) ? mb1 : mb0;
        if (w < 8) bulk_issue(dst, WgH + w * (32 * 512), 32 * 512 * 4, mb);
        else       bulk_issue(dst, WcH + (w - 8) * (32 * 256), 32 * 256 * 4, mb);
    };

    if (tid == 0) { issue_tile(0); issue_tile(1); }

    int gofs = dir ? 768 : 0;
    int cofs = dir ? 1280 : 512;
    int j = tid;
    int tc = 0;

    for (int t = 0; t < maxlen; t++) {
        float a0 = 0.f, a1 = 0.f;
        for (int w = 0; w < 8; w++, tc++) {
            const float* wb = (tc & 1) ? buf1 : buf0;
            mbar_wait((tc & 1) ? mb1 : mb0, (tc >> 1) & 1);
            int k0 = w * 32;
#pragma unroll
            for (int k4 = 0; k4 < 8; k4++) {
                float w0 = wb[(k4 * 4 + 0) * 512 + j];
                float w1 = wb[(k4 * 4 + 1) * 512 + j];
                float w2 = wb[(k4 * 4 + 2) * 512 + j];
                float w3 = wb[(k4 * 4 + 3) * 512 + j];
                float4 h0 = *(const float4*)(hst + k0 + k4 * 4);
                float4 h1 = *(const float4*)(hst + 256 + k0 + k4 * 4);
                a0 += h0.x * w0 + h0.y * w1 + h0.z * w2 + h0.w * w3;
                a1 += h1.x * w0 + h1.y * w1 + h1.z * w2 + h1.w * w3;
            }
            __syncthreads();
            if (tid == 0) issue_tile(tc + 2);
        }
#pragma unroll
        for (int d = 0; d < 2; d++) {
            float acc = d ? a1 : a0;
            int len = dlen[d];
            bool valid = t < len;
            float g = 0.f;
            if (valid) {
                int widx = dir ? (len - 1 - t) : t;
                float p = g_dpre[(docid[d] * 32 + widx) * 1536 + gofs + j];
                g = 1.f / (1.f + __expf(-(acc + p)));
            }
            if (j < 256) rhst[d * 256 + j]         = valid ? g * hst[d * 256 + j] : 0.f;
            else         ust [d * 256 + (j - 256)] = valid ? g : 1.f;
        }
        __syncthreads();

        float c0a = 0.f, c1a = 0.f;
        for (int w = 0; w < 8; w++, tc++) {
            const float* wb = (tc & 1) ? buf1 : buf0;
            mbar_wait((tc & 1) ? mb1 : mb0, (tc >> 1) & 1);
            if (tid < 256) {
                int k0 = w * 32;
#pragma unroll
                for (int k4 = 0; k4 < 8; k4++) {
                    float w0 = wb[(k4 * 4 + 0) * 256 + tid];
                    float w1 = wb[(k4 * 4 + 1) * 256 + tid];
                    float w2 = wb[(k4 * 4 + 2) * 256 + tid];
                    float w3 = wb[(k4 * 4 + 3) * 256 + tid];
                    float4 r0 = *(const float4*)(rhst + k0 + k4 * 4);
                    float4 r1 = *(const float4*)(rhst + 256 + k0 + k4 * 4);
                    c0a += r0.x * w0 + r0.y * w1 + r0.z * w2 + r0.w * w3;
                    c1a += r1.x * w0 + r1.y * w1 + r1.z * w2 + r1.w * w3;
                }
            }
            __syncthreads();
            if (tid == 0) issue_tile(tc + 2);
        }
        if (tid < 256) {
#pragma unroll
            for (int d = 0; d < 2; d++) {
                int len = dlen[d];
                if (t < len) {
                    int widx = dir ? (len - 1 - t) : t;
                    float p = g_dpre[(docid[d] * 32 + widx) * 1536 + cofs + tid];
                    float c = tanhf((d ? c1a : c0a) + p);
                    float uu = ust[d * 256 + tid];
                    hst[d * 256 + tid] = uu * hst[d * 256 + tid] + (1.f - uu) * c;
                }
            }
        }
        __syncthreads();
    }

    {
        int d = tid >> 8, jc = tid & 255;
        g_doc[docid[d] * 512 + dir * 256 + jc] = hst[d * 256 + jc];
    }
}

// ---------------- K5: MLP hidden GEMM + relu ----------------
__global__ void __launch_bounds__(256) k5_mlp1(
    const float* __restrict__ W1, const float* __restrict__ b1)
{
    extern __shared__ float sm[];
    float* Ash = sm;
    float* Bsh = sm + 64 * 129;
    int col0 = blockIdx.x * 64;
    int tid = threadIdx.x;
    int r0 = (tid >> 4) * 4, c0 = (tid & 15) * 4;
    float acc[4][4];
#pragma unroll
    for (int q = 0; q < 4; q++)
#pragma unroll
        for (int c = 0; c < 4; c++) acc[q][c] = 0.f;

    for (int ch = 0; ch < 4; ch++) {
#pragma unroll
        for (int i = 0; i < 8; i++) {
            int f = tid + i * 256;
            int row = f >> 5, c4 = f & 31;
            float4 v = *(const float4*)(g_doc + row * 512 + ch * 128 + c4 * 4);
            Ash[row * 129 + c4 * 4 + 0] = v.x;
            Ash[row * 129 + c4 * 4 + 1] = v.y;
            Ash[row * 129 + c4 * 4 + 2] = v.z;
            Ash[row * 129 + c4 * 4 + 3] = v.w;
        }
#pragma unroll
        for (int i = 0; i < 8; i++) {
            int f = tid + i * 256;
            int k = f >> 4, c4 = f & 15;
            float4 v = __ldg((const float4*)(W1 + (ch * 128 + k) * 256 + col0) + c4);
            *(float4*)(Bsh + k * 64 + c4 * 4) = v;
        }
        __syncthreads();
#pragma unroll 8
        for (int k = 0; k < 128; k++) {
            float a0 = Ash[(r0 + 0) * 129 + k];
            float a1 = Ash[(r0 + 1) * 129 + k];
            float a2 = Ash[(r0 + 2) * 129 + k];
            float a3 = Ash[(r0 + 3) * 129 + k];
            float4 b = *(float4*)(Bsh + k * 64 + c0);
            acc[0][0] += a0 * b.x; acc[0][1] += a0 * b.y; acc[0][2] += a0 * b.z; acc[0][3] += a0 * b.w;
            acc[1][0] += a1 * b.x; acc[1][1] += a1 * b.y; acc[1][2] += a1 * b.z; acc[1][3] += a1 * b.w;
            acc[2][0] += a2 * b.x; acc[2][1] += a2 * b.y; acc[2][2] += a2 * b.z; acc[2][3] += a2 * b.w;
            acc[3][0] += a3 * b.x; acc[3][1] += a3 * b.y; acc[3][2] += a3 * b.z; acc[3][3] += a3 * b.w;
        }
        __syncthreads();
    }

    float4 bv = *(const float4*)(b1 + col0 + c0);
#pragma unroll
    for (int q = 0; q < 4; q++) {
        float4 o;
        o.x = fmaxf(acc[q][0] + bv.x, 0.f); o.y = fmaxf(acc[q][1] + bv.y, 0.f);
        o.z = fmaxf(acc[q][2] + bv.z, 0.f); o.w = fmaxf(acc[q][3] + bv.w, 0.f);
        *(float4*)(g_hid + (r0 + q) * 256 + col0 + c0) = o;
    }
}

// ---------------- K6: logits ----------------
__global__ void __launch_bounds__(512) k6_logits(
    const float* __restrict__ W2, const float* __restrict__ b2,
    float* __restrict__ out)
{
    extern __shared__ float sm[];
    float* hidS = sm;
    float* W2s  = sm + 16384;
    int tid = threadIdx.x;
    for (int i = tid; i < 16384; i += 512) hidS[i] = g_hid[i];
    for (int i = tid; i < 1280; i += 512) W2s[i] = W2[i];
    __syncthreads();
    if (tid < 320) {
        int doc = tid / 5, o = tid % 5;
        float acc = b2[o];
#pragma unroll 8
        for (int k = 0; k < 256; k++)
            acc += hidS[doc * 256 + k] * W2s[k * 5 + o];
        out[doc * 5 + o] = acc;
    }
}

// ---------------- launcher ----------------
extern "C" void kernel_launch(void* const* d_in, const int* in_sizes, int n_in,
                              void* d_out, int out_size)
{
    const int*   X     = (const int*)d_in[0];
    const int*   L     = (const int*)d_in[1];
    const int*   L2    = (const int*)d_in[2];
    const float* emb   = (const float*)d_in[3];
    const float* sWg_f = (const float*)d_in[4];
    const float* sbg_f = (const float*)d_in[5];
    const float* sWc_f = (const float*)d_in[6];
    const float* sbc_f = (const float*)d_in[7];
    const float* sWg_b = (const float*)d_in[8];
    const float* sbg_b = (const float*)d_in[9];
    const float* sWc_b = (const float*)d_in[10];
    const float* sbc_b = (const float*)d_in[11];
    const float* dWg_f = (const float*)d_in[12];
    const float* dbg_f = (const float*)d_in[13];
    const float* dWc_f = (const float*)d_in[14];
    const float* dbc_f = (const float*)d_in[15];
    const float* dWg_b = (const float*)d_in[16];
    const float* dbg_b = (const float*)d_in[17];
    const float* dWc_b = (const float*)d_in[18];
    const float* dbc_b = (const float*)d_in[19];
    const float* W1    = (const float*)d_in[20];
    const float* b1    = (const float*)d_in[21];
    const float* W2    = (const float*)d_in[22];
    const float* b2    = (const float*)d_in[23];
    float* out = (float*)d_out;

    cudaFuncSetAttribute(k1_wordgemm, cudaFuncAttributeMaxDynamicSharedMemorySize, SMEM_K1);
    cudaFuncSetAttribute(k2_sentgru,  cudaFuncAttributeMaxDynamicSharedMemorySize, SMEM_K2);
    cudaFuncSetAttribute(k3_docgemm,  cudaFuncAttributeMaxDynamicSharedMemorySize, SMEM_GEMM);
    cudaFuncSetAttribute(k4_docgru,   cudaFuncAttributeMaxDynamicSharedMemorySize, SMEM_K4);
    cudaFuncSetAttribute(k5_mlp1,     cudaFuncAttributeMaxDynamicSharedMemorySize, SMEM_GEMM);
    cudaFuncSetAttribute(k6_logits,   cudaFuncAttributeMaxDynamicSharedMemorySize, SMEM_K6);

    // k0 split into two launches: shifts ncu's captured launch index by one so
    // the profile lands on k2_sentgru instead of k3_docgemm (measurement round).
    k0a_sort<<<1, 256>>>(L);
    k0b_sort<<<1, 256>>>(L2);
    dim3 g1(2048, 12);
    k1_wordgemm<<<g1, 256, SMEM_K1>>>(X, L, emb, sWg_f, sbg_f, sWc_f, sbc_f,
                                      sWg_b, sbg_b, sWc_b, sbc_b);
    k2_sentgru<<<256, 512, SMEM_K2>>>(L, sWg_f, sWc_f, sWg_b, sWc_b);
    dim3 g3(32, 24);
    k3_docgemm<<<g3, 256, SMEM_GEMM>>>(dWg_f, dbg_f, dWc_f, dbc_f,
                                       dWg_b, dbg_b, dWc_b, dbc_b);
    k4_docgru<<<64, 512, SMEM_K4>>>(dWg_f, dWc_f, dWg_b, dWc_b, L2);
    k5_mlp1<<<4, 256, SMEM_GEMM>>>(W1, b1);
    k6_logits<<<1, 512, SMEM_K6>>>(W2, b2, out);
}

// round 16
// speedup vs baseline: 1.1608x; 1.1359x over previous
#include <cuda_runtime.h>
#include <math.h>

#define NSENT 2048
#define BB    64

__device__ float g_pre [(size_t)NSENT * 64 * 768];
__device__ float g_sent[NSENT * 256];
__device__ float g_dpre[NSENT * 1536];
__device__ float g_doc [BB * 512];
__device__ float g_hid [BB * 256];
__device__ int   g_order_s[NSENT];
__device__ int   g_order_d[BB];

#define SMEM_K1   (2 * 64 * 132 * 4)                    // 67584
#define SMEM_K2   ((256*132 + 128*132 + 3*16*132) * 4)  // 228096
#define SMEM_GEMM ((64*129 + 128*64) * 4)
#define SMEM_K4   ((32768 + 1536) * 4)                  // 137216
#define SMEM_K6   ((16384 + 1280) * 4)

// packed f32x2 fma (SASS FFMA2)
__device__ __forceinline__ void ffma2(unsigned long long& d,
                                      unsigned long long a,
                                      unsigned long long b) {
    asm("fma.rn.f32x2 %0, %1, %2, %0;" : "+l"(d) : "l"(a), "l"(b));
}
__device__ __forceinline__ float f2sum(unsigned long long v) {
    return __uint_as_float((unsigned)v) + __uint_as_float((unsigned)(v >> 32));
}
__device__ __forceinline__ unsigned tf32r(float x) {
    unsigned u; asm("cvt.rna.tf32.f32 %0, %1;" : "=r"(u) : "f"(x)); return u;
}
__device__ __forceinline__ void mma8(float c[4], const unsigned a[4], const unsigned b[2]) {
    asm("mma.sync.aligned.m16n8k8.row.col.f32.tf32.tf32.f32 "
        "{%0,%1,%2,%3},{%4,%5,%6,%7},{%8,%9},{%0,%1,%2,%3};"
        : "+f"(c[0]), "+f"(c[1]), "+f"(c[2]), "+f"(c[3])
        : "r"(a[0]), "r"(a[1]), "r"(a[2]), "r"(a[3]), "r"(b[0]), "r"(b[1]));
}
__device__ __forceinline__ unsigned smem_u32(const void* p) {
    return (unsigned)__cvta_generic_to_shared(p);
}
__device__ __forceinline__ void mbar_wait(unsigned mbar, unsigned phase) {
    asm volatile(
        "{\n\t.reg .pred P;\n\t"
        "LW%=:\n\t"
        "mbarrier.try_wait.parity.shared::cta.b64 P, [%0], %1, 0x989680;\n\t"
        "@P bra LD%=;\n\t"
        "bra LW%=;\n\t"
        "LD%=:\n\t}"
        :: "r"(mbar), "r"(phase) : "memory");
}
__device__ __forceinline__ void bulk_issue(unsigned dst, const void* src,
                                           unsigned bytes, unsigned mbar) {
    asm volatile("mbarrier.arrive.expect_tx.shared.b64 _, [%0], %1;"
                 :: "r"(mbar), "r"(bytes) : "memory");
    asm volatile(
        "cp.async.bulk.shared::cluster.global.mbarrier::complete_tx::bytes "
        "[%0], [%1], %2, [%3];"
        :: "r"(dst), "l"(src), "r"(bytes), "r"(mbar) : "memory");
}

// ---------------- K0a: sentence counting sort ----------------
__global__ void k0a_sort(const int* __restrict__ L)
{
    int tid = threadIdx.x;
    __shared__ int lens[NSENT];
    __shared__ int cnt[64];
    for (int i = tid; i < NSENT; i += 256) lens[i] = L[i];
    if (tid < 64) cnt[tid] = 0;
    __syncthreads();
    for (int i = tid; i < NSENT; i += 256) atomicAdd(&cnt[lens[i]], 1);
    __syncthreads();
    if (tid < 64) {
        int o = 0;
        for (int u = 0; u < tid; u++) o += cnt[u];
        for (int i = 0; i < NSENT; i++)
            if (lens[i] == tid) g_order_s[o++] = i;
    }
}

// ---------------- K0b: doc counting sort ----------------
__global__ void k0b_sort(const int* __restrict__ L2)
{
    int tid = threadIdx.x;
    __shared__ int l2s[BB];
    __shared__ int cnt2[32];
    if (tid < BB) l2s[tid] = L2[tid];
    if (tid < 32) cnt2[tid] = 0;
    __syncthreads();
    if (tid < BB) atomicAdd(&cnt2[l2s[tid]], 1);
    __syncthreads();
    if (tid < 32) {
        int o = 0;
        for (int u = 0; u < tid; u++) o += cnt2[u];
        for (int i = 0; i < BB; i++)
            if (l2s[i] == tid) g_order_d[o++] = i;
    }
}

// ---------------- K1: word embed + x-projection GEMM (FFMA2) ----------------
__global__ void __launch_bounds__(256) k1_wordgemm(
    const int* __restrict__ X, const int* __restrict__ L,
    const float* __restrict__ emb,
    const float* __restrict__ sWg_f, const float* __restrict__ sbg_f,
    const float* __restrict__ sWc_f, const float* __restrict__ sbc_f,
    const float* __restrict__ sWg_b, const float* __restrict__ sbg_b,
    const float* __restrict__ sWc_b, const float* __restrict__ sbc_b)
{
    extern __shared__ float sm[];
    float* Ash  = sm;               // [64][132]
    float* BshT = sm + 64 * 132;    // [64 cols][132 k]

    int s    = blockIdx.x;
    int col0 = blockIdx.y * 64;
    int len  = L[s];
    const float* src; const float* bias; int ldN, cofs;
    if (col0 < 256)      { src = sWg_f; bias = sbg_f; ldN = 256; cofs = col0;       }
    else if (col0 < 384) { src = sWc_f; bias = sbc_f; ldN = 128; cofs = col0 - 256; }
    else if (col0 < 640) { src = sWg_b; bias = sbg_b; ldN = 256; cofs = col0 - 384; }
    else                 { src = sWc_b; bias = sbc_b; ldN = 128; cofs = col0 - 640; }

    int tid = threadIdx.x;
#pragma unroll
    for (int i = 0; i < 8; i++) {
        int f = tid + i * 256;
        int row = f >> 5, c4 = f & 31;
        if (row < len) {
            int wid = X[s * 64 + row];
            float4 v = __ldg((const float4*)(emb + (size_t)wid * 128) + c4);
            *(float4*)(Ash + row * 132 + c4 * 4) = v;
        }
    }
    {
        int c = tid & 63;
        const float* colp = src + cofs + c;
#pragma unroll
        for (int kq = (tid >> 6) * 4; kq < 128; kq += 16) {
            float4 v;
            v.x = __ldg(colp + (kq + 0) * ldN);
            v.y = __ldg(colp + (kq + 1) * ldN);
            v.z = __ldg(colp + (kq + 2) * ldN);
            v.w = __ldg(colp + (kq + 3) * ldN);
            *(float4*)(BshT + c * 132 + kq) = v;
        }
    }
    __syncthreads();

    int r0    = (tid >> 4) * 4;
    int cbase = tid & 15;
    if (r0 >= len) return;

    unsigned long long acc2[4][4];
#pragma unroll
    for (int q = 0; q < 4; q++)
#pragma unroll
        for (int c = 0; c < 4; c++) acc2[q][c] = 0ull;

#pragma unroll 4
    for (int k = 0; k < 128; k += 4) {
        ulonglong2 a[4], b[4];
#pragma unroll
        for (int q = 0; q < 4; q++)
            a[q] = *(const ulonglong2*)(Ash + (r0 + q) * 132 + k);
#pragma unroll
        for (int c = 0; c < 4; c++)
            b[c] = *(const ulonglong2*)(BshT + (cbase + c * 16) * 132 + k);
#pragma unroll
        for (int q = 0; q < 4; q++)
#pragma unroll
            for (int c = 0; c < 4; c++) {
                ffma2(acc2[q][c], a[q].x, b[c].x);
                ffma2(acc2[q][c], a[q].y, b[c].y);
            }
    }

#pragma unroll
    for (int q = 0; q < 4; q++) {
        if (r0 + q < len) {
            float* op = g_pre + ((size_t)s * 64 + r0 + q) * 768 + col0;
#pragma unroll
            for (int c = 0; c < 4; c++) {
                int cl = cbase + c * 16;
                op[cl] = f2sum(acc2[q][c]) + __ldg(bias + cofs + cl);
            }
        }
    }
}

// ---------------- K2: sentence bi-GRU, tf32 MMA + prefetched g_pre ----------
__global__ void __launch_bounds__(512) k2_sentgru(
    const int* __restrict__ L,
    const float* __restrict__ sWg_f, const float* __restrict__ sWc_f,
    const float* __restrict__ sWg_b, const float* __restrict__ sWc_b)
{
    extern __shared__ float sm[];
    unsigned* WgTu = (unsigned*)sm;            // [256 j][132 k]
    unsigned* WcTu = WgTu + 256 * 132;         // [128 j][132 k]
    float* hS  = (float*)(WcTu + 128 * 132);   // [16][132]
    float* rhS = hS  + 16 * 132;
    float* uS  = rhS + 16 * 132;
    __shared__ int slen[16], sid[16], smax;

    int dir = blockIdx.x & 1;
    int grp = 127 - (blockIdx.x >> 1);
    int tid = threadIdx.x;

    const float* wgsrc = (dir ? sWg_b : sWg_f) + 128 * 256;
    const float* wcsrc = (dir ? sWc_b : sWc_f) + 128 * 128;

    {
        int j = tid & 255;
        const float* colp = wgsrc + j;
#pragma unroll
        for (int kq = (tid >> 8) * 4; kq < 128; kq += 8) {
            WgTu[j * 132 + kq + 0] = tf32r(__ldg(colp + (kq + 0) * 256));
            WgTu[j * 132 + kq + 1] = tf32r(__ldg(colp + (kq + 1) * 256));
            WgTu[j * 132 + kq + 2] = tf32r(__ldg(colp + (kq + 2) * 256));
            WgTu[j * 132 + kq + 3] = tf32r(__ldg(colp + (kq + 3) * 256));
        }
    }
    {
        int j = tid & 127;
        const float* colp = wcsrc + j;
#pragma unroll
        for (int kq = (tid >> 7) * 4; kq < 128; kq += 16) {
            WcTu[j * 132 + kq + 0] = tf32r(__ldg(colp + (kq + 0) * 128));
            WcTu[j * 132 + kq + 1] = tf32r(__ldg(colp + (kq + 1) * 128));
            WcTu[j * 132 + kq + 2] = tf32r(__ldg(colp + (kq + 2) * 128));
            WcTu[j * 132 + kq + 3] = tf32r(__ldg(colp + (kq + 3) * 128));
        }
    }
    if (tid < 16) {
        int ss = g_order_s[grp * 16 + tid];
        sid[tid]  = ss;
        slen[tid] = L[ss];
    }
    for (int i = tid; i < 16 * 132; i += 512) hS[i] = 0.f;
    __syncthreads();
    if (tid == 0) {
        int m = 0;
        for (int i = 0; i < 16; i++) m = max(m, slen[i]);
        smax = m;
    }
    __syncthreads();
    int maxlen = smax;

    int wrp = tid >> 5, lane = tid & 31;
    int g = lane >> 2, tig = lane & 3;
    int jbase = wrp * 16;
    int jc0   = wrp * 8;
    int gbase = dir ? 384 : 0;
    int cbase = dir ? 640 : 256;

    // per-thread row bases for the two fragment rows (g and g+8)
    for (int t = 0; t < maxlen; t++) {
        // ---- prefetch ALL g_pre values for this step (overlaps MMA latency) ----
        float pg[2][4];   // gates pre: [tl][e]
        float pc[4];      // candidate pre: [e]
#pragma unroll
        for (int e = 0; e < 4; e++) {
            int r = (e < 2) ? g : g + 8;
            int len = slen[r];
            bool valid = t < len;
            size_t rowoff = 0;
            if (valid) {
                int widx = dir ? (len - 1 - t) : t;
                rowoff = ((size_t)sid[r] * 64 + widx) * 768;
            }
#pragma unroll
            for (int tl = 0; tl < 2; tl++) {
                int j = jbase + tl * 8 + 2 * tig + (e & 1);
                pg[tl][e] = valid ? __ldg(g_pre + rowoff + gbase + j) : 0.f;
            }
            int jc = jc0 + 2 * tig + (e & 1);
            pc[e] = valid ? __ldg(g_pre + rowoff + cbase + jc) : 0.f;
        }

        // ---- gates GEMM ----
        float c0[4] = {0,0,0,0}, c1[4] = {0,0,0,0};
#pragma unroll
        for (int k = 0; k < 128; k += 8) {
            unsigned a[4], b0[2], b1[2];
            a[0] = tf32r(hS[g * 132 + k + tig]);
            a[1] = tf32r(hS[(g + 8) * 132 + k + tig]);
            a[2] = tf32r(hS[g * 132 + k + 4 + tig]);
            a[3] = tf32r(hS[(g + 8) * 132 + k + 4 + tig]);
            b0[0] = WgTu[(jbase + g) * 132 + k + tig];
            b0[1] = WgTu[(jbase + g) * 132 + k + 4 + tig];
            b1[0] = WgTu[(jbase + 8 + g) * 132 + k + tig];
            b1[1] = WgTu[(jbase + 8 + g) * 132 + k + 4 + tig];
            mma8(c0, a, b0);
            mma8(c1, a, b1);
        }
#pragma unroll
        for (int tl = 0; tl < 2; tl++) {
            float* cc = tl ? c1 : c0;
#pragma unroll
            for (int e = 0; e < 4; e++) {
                int r = (e < 2) ? g : g + 8;
                int j = jbase + tl * 8 + 2 * tig + (e & 1);
                bool valid = t < slen[r];
                float gg = 0.f;
                if (valid)
                    gg = 1.f / (1.f + __expf(-(cc[e] + pg[tl][e])));
                if (j < 128) rhS[r * 132 + j]       = valid ? gg * hS[r * 132 + j] : 0.f;
                else         uS [r * 132 + j - 128] = valid ? gg : 1.f;
            }
        }
        __syncthreads();

        // ---- candidate GEMM ----
        float cc[4] = {0,0,0,0};
#pragma unroll
        for (int k = 0; k < 128; k += 8) {
            unsigned a[4], b[2];
            a[0] = tf32r(rhS[g * 132 + k + tig]);
            a[1] = tf32r(rhS[(g + 8) * 132 + k + tig]);
            a[2] = tf32r(rhS[g * 132 + k + 4 + tig]);
            a[3] = tf32r(rhS[(g + 8) * 132 + k + 4 + tig]);
            b[0] = WcTu[(jc0 + g) * 132 + k + tig];
            b[1] = WcTu[(jc0 + g) * 132 + k + 4 + tig];
            mma8(cc, a, b);
        }
#pragma unroll
        for (int e = 0; e < 4; e++) {
            int r = (e < 2) ? g : g + 8;
            int jc = jc0 + 2 * tig + (e & 1);
            if (t < slen[r]) {
                float c = tanhf(cc[e] + pc[e]);
                float u = uS[r * 132 + jc];
                hS[r * 132 + jc] = u * hS[r * 132 + jc] + (1.f - u) * c;
            }
        }
        __syncthreads();
    }

#pragma unroll
    for (int e = 0; e < 4; e++) {
        int r = (e < 2) ? g : g + 8;
        int jc = jc0 + 2 * tig + (e & 1);
        g_sent[sid[r] * 256 + dir * 128 + jc] = hS[r * 132 + jc];
    }
}

// ---------------- K3: doc x-projection GEMM ----------------
__global__ void __launch_bounds__(256) k3_docgemm(
    const float* __restrict__ dWg_f, const float* __restrict__ dbg_f,
    const float* __restrict__ dWc_f, const float* __restrict__ dbc_f,
    const float* __restrict__ dWg_b, const float* __restrict__ dbg_b,
    const float* __restrict__ dWc_b, const float* __restrict__ dbc_b)
{
    extern __shared__ float sm[];
    float* Ash = sm;
    float* Bsh = sm + 64 * 129;

    int rb   = blockIdx.x;
    int col0 = blockIdx.y * 64;
    const float* src; const float* bias; int ldN, cofs;
    if (col0 < 512)       { src = dWg_f; bias = dbg_f; ldN = 512; cofs = col0;        }
    else if (col0 < 768)  { src = dWc_f; bias = dbc_f; ldN = 256; cofs = col0 - 512;  }
    else if (col0 < 1280) { src = dWg_b; bias = dbg_b; ldN = 512; cofs = col0 - 768;  }
    else                  { src = dWc_b; bias = dbc_b; ldN = 256; cofs = col0 - 1280; }

    int tid = threadIdx.x;
    int r0 = (tid >> 4) * 4;
    int c0 = (tid & 15) * 4;
    float acc[4][4];
#pragma unroll
    for (int q = 0; q < 4; q++)
#pragma unroll
        for (int c = 0; c < 4; c++) acc[q][c] = 0.f;

    for (int ch = 0; ch < 2; ch++) {
#pragma unroll
        for (int i = 0; i < 8; i++) {
            int f = tid + i * 256;
            int row = f >> 5, c4 = f & 31;
            float4 v = *(const float4*)(g_sent + (rb * 64 + row) * 256 + ch * 128 + c4 * 4);
            Ash[row * 129 + c4 * 4 + 0] = v.x;
            Ash[row * 129 + c4 * 4 + 1] = v.y;
            Ash[row * 129 + c4 * 4 + 2] = v.z;
            Ash[row * 129 + c4 * 4 + 3] = v.w;
        }
#pragma unroll
        for (int i = 0; i < 8; i++) {
            int f = tid + i * 256;
            int k = f >> 4, c4 = f & 15;
            float4 v = __ldg((const float4*)(src + (ch * 128 + k) * ldN + cofs) + c4);
            *(float4*)(Bsh + k * 64 + c4 * 4) = v;
        }
        __syncthreads();
#pragma unroll 8
        for (int k = 0; k < 128; k++) {
            float a0 = Ash[(r0 + 0) * 129 + k];
            float a1 = Ash[(r0 + 1) * 129 + k];
            float a2 = Ash[(r0 + 2) * 129 + k];
            float a3 = Ash[(r0 + 3) * 129 + k];
            float4 b = *(float4*)(Bsh + k * 64 + c0);
            acc[0][0] += a0 * b.x; acc[0][1] += a0 * b.y; acc[0][2] += a0 * b.z; acc[0][3] += a0 * b.w;
            acc[1][0] += a1 * b.x; acc[1][1] += a1 * b.y; acc[1][2] += a1 * b.z; acc[1][3] += a1 * b.w;
            acc[2][0] += a2 * b.x; acc[2][1] += a2 * b.y; acc[2][2] += a2 * b.z; acc[2][3] += a2 * b.w;
            acc[3][0] += a3 * b.x; acc[3][1] += a3 * b.y; acc[3][2] += a3 * b.z; acc[3][3] += a3 * b.w;
        }
        __syncthreads();
    }

    float4 bv = *(const float4*)(bias + cofs + c0);
#pragma unroll
    for (int q = 0; q < 4; q++) {
        float4 o;
        o.x = acc[q][0] + bv.x; o.y = acc[q][1] + bv.y;
        o.z = acc[q][2] + bv.z; o.w = acc[q][3] + bv.w;
        *(float4*)(g_dpre + (size_t)(rb * 64 + r0 + q) * 1536 + col0 + c0) = o;
    }
}

// ---------------- K4: doc bi-GRU, 2 docs/block, bulk-streamed weights -------
__global__ void __launch_bounds__(512) k4_docgru(
    const float* __restrict__ dWg_f, const float* __restrict__ dWc_f,
    const float* __restrict__ dWg_b, const float* __restrict__ dWc_b,
    const int* __restrict__ L2)
{
    extern __shared__ float sm[];
    float* buf0 = sm;
    float* buf1 = sm + 16384;
    float* hst  = sm + 32768;
    float* rhst = hst + 512;
    float* ust  = rhst + 512;
    __shared__ unsigned long long mbar[2];
    __shared__ int docid[2], dlen[2];

    int dir = blockIdx.x & 1;
    int grp = 31 - (blockIdx.x >> 1);
    int tid = threadIdx.x;

    const float* WgH = (dir ? dWg_b : dWg_f) + 256 * 512;
    const float* WcH = (dir ? dWc_b : dWc_f) + 256 * 256;

    if (tid < 2) {
        int dd = g_order_d[grp * 2 + tid];
        docid[tid] = dd;
        dlen[tid] = L2[dd];
    }
    hst[tid] = 0.f;
    if (tid == 0) {
        asm volatile("mbarrier.init.shared.b64 [%0], 1;" :: "r"(smem_u32(&mbar[0])) : "memory");
        asm volatile("mbarrier.init.shared.b64 [%0], 1;" :: "r"(smem_u32(&mbar[1])) : "memory");
        asm volatile("fence.proxy.async;" ::: "memory");
    }
    __syncthreads();

    int maxlen = max(dlen[0], dlen[1]);
    int ntiles = maxlen * 16;
    unsigned mb0 = smem_u32(&mbar[0]), mb1 = smem_u32(&mbar[1]);
    unsigned ba0 = smem_u32(buf0),     ba1 = smem_u32(buf1);

    auto issue_tile = [&](int tt) {
        if (tt >= ntiles) return;
        int w = tt & 15;
        unsigned dst = (tt & 1) ? ba1 : ba0;
        unsigned mb  = (tt & 1) ? mb1 : mb0;
        if (w < 8) bulk_issue(dst, WgH + w * (32 * 512), 32 * 512 * 4, mb);
        else       bulk_issue(dst, WcH + (w - 8) * (32 * 256), 32 * 256 * 4, mb);
    };

    if (tid == 0) { issue_tile(0); issue_tile(1); }

    int gofs = dir ? 768 : 0;
    int cofs = dir ? 1280 : 512;
    int j = tid;
    int tc = 0;

    for (int t = 0; t < maxlen; t++) {
        float a0 = 0.f, a1 = 0.f;
        for (int w = 0; w < 8; w++, tc++) {
            const float* wb = (tc & 1) ? buf1 : buf0;
            mbar_wait((tc & 1) ? mb1 : mb0, (tc >> 1) & 1);
            int k0 = w * 32;
#pragma unroll
            for (int k4 = 0; k4 < 8; k4++) {
                float w0 = wb[(k4 * 4 + 0) * 512 + j];
                float w1 = wb[(k4 * 4 + 1) * 512 + j];
                float w2 = wb[(k4 * 4 + 2) * 512 + j];
                float w3 = wb[(k4 * 4 + 3) * 512 + j];
                float4 h0 = *(const float4*)(hst + k0 + k4 * 4);
                float4 h1 = *(const float4*)(hst + 256 + k0 + k4 * 4);
                a0 += h0.x * w0 + h0.y * w1 + h0.z * w2 + h0.w * w3;
                a1 += h1.x * w0 + h1.y * w1 + h1.z * w2 + h1.w * w3;
            }
            __syncthreads();
            if (tid == 0) issue_tile(tc + 2);
        }
#pragma unroll
        for (int d = 0; d < 2; d++) {
            float acc = d ? a1 : a0;
            int len = dlen[d];
            bool valid = t < len;
            float g = 0.f;
            if (valid) {
                int widx = dir ? (len - 1 - t) : t;
                float p = g_dpre[(docid[d] * 32 + widx) * 1536 + gofs + j];
                g = 1.f / (1.f + __expf(-(acc + p)));
            }
            if (j < 256) rhst[d * 256 + j]         = valid ? g * hst[d * 256 + j] : 0.f;
            else         ust [d * 256 + (j - 256)] = valid ? g : 1.f;
        }
        __syncthreads();

        float c0a = 0.f, c1a = 0.f;
        for (int w = 0; w < 8; w++, tc++) {
            const float* wb = (tc & 1) ? buf1 : buf0;
            mbar_wait((tc & 1) ? mb1 : mb0, (tc >> 1) & 1);
            if (tid < 256) {
                int k0 = w * 32;
#pragma unroll
                for (int k4 = 0; k4 < 8; k4++) {
                    float w0 = wb[(k4 * 4 + 0) * 256 + tid];
                    float w1 = wb[(k4 * 4 + 1) * 256 + tid];
                    float w2 = wb[(k4 * 4 + 2) * 256 + tid];
                    float w3 = wb[(k4 * 4 + 3) * 256 + tid];
                    float4 r0 = *(const float4*)(rhst + k0 + k4 * 4);
                    float4 r1 = *(const float4*)(rhst + 256 + k0 + k4 * 4);
                    c0a += r0.x * w0 + r0.y * w1 + r0.z * w2 + r0.w * w3;
                    c1a += r1.x * w0 + r1.y * w1 + r1.z * w2 + r1.w * w3;
                }
            }
            __syncthreads();
            if (tid == 0) issue_tile(tc + 2);
        }
        if (tid < 256) {
#pragma unroll
            for (int d = 0; d < 2; d++) {
                int len = dlen[d];
                if (t < len) {
                    int widx = dir ? (len - 1 - t) : t;
                    float p = g_dpre[(docid[d] * 32 + widx) * 1536 + cofs + tid];
                    float c = tanhf((d ? c1a : c0a) + p);
                    float uu = ust[d * 256 + tid];
                    hst[d * 256 + tid] = uu * hst[d * 256 + tid] + (1.f - uu) * c;
                }
            }
        }
        __syncthreads();
    }

    {
        int d = tid >> 8, jc = tid & 255;
        g_doc[docid[d] * 512 + dir * 256 + jc] = hst[d * 256 + jc];
    }
}

// ---------------- K5: MLP hidden GEMM + relu ----------------
__global__ void __launch_bounds__(256) k5_mlp1(
    const float* __restrict__ W1, const float* __restrict__ b1)
{
    extern __shared__ float sm[];
    float* Ash = sm;
    float* Bsh = sm + 64 * 129;
    int col0 = blockIdx.x * 64;
    int tid = threadIdx.x;
    int r0 = (tid >> 4) * 4, c0 = (tid & 15) * 4;
    float acc[4][4];
#pragma unroll
    for (int q = 0; q < 4; q++)
#pragma unroll
        for (int c = 0; c < 4; c++) acc[q][c] = 0.f;

    for (int ch = 0; ch < 4; ch++) {
#pragma unroll
        for (int i = 0; i < 8; i++) {
            int f = tid + i * 256;
            int row = f >> 5, c4 = f & 31;
            float4 v = *(const float4*)(g_doc + row * 512 + ch * 128 + c4 * 4);
            Ash[row * 129 + c4 * 4 + 0] = v.x;
            Ash[row * 129 + c4 * 4 + 1] = v.y;
            Ash[row * 129 + c4 * 4 + 2] = v.z;
            Ash[row * 129 + c4 * 4 + 3] = v.w;
        }
#pragma unroll
        for (int i = 0; i < 8; i++) {
            int f = tid + i * 256;
            int k = f >> 4, c4 = f & 15;
            float4 v = __ldg((const float4*)(W1 + (ch * 128 + k) * 256 + col0) + c4);
            *(float4*)(Bsh + k * 64 + c4 * 4) = v;
        }
        __syncthreads();
#pragma unroll 8
        for (int k = 0; k < 128; k++) {
            float a0 = Ash[(r0 + 0) * 129 + k];
            float a1 = Ash[(r0 + 1) * 129 + k];
            float a2 = Ash[(r0 + 2) * 129 + k];
            float a3 = Ash[(r0 + 3) * 129 + k];
            float4 b = *(float4*)(Bsh + k * 64 + c0);
            acc[0][0] += a0 * b.x; acc[0][1] += a0 * b.y; acc[0][2] += a0 * b.z; acc[0][3] += a0 * b.w;
            acc[1][0] += a1 * b.x; acc[1][1] += a1 * b.y; acc[1][2] += a1 * b.z; acc[1][3] += a1 * b.w;
            acc[2][0] += a2 * b.x; acc[2][1] += a2 * b.y; acc[2][2] += a2 * b.z; acc[2][3] += a2 * b.w;
            acc[3][0] += a3 * b.x; acc[3][1] += a3 * b.y; acc[3][2] += a3 * b.z; acc[3][3] += a3 * b.w;
        }
        __syncthreads();
    }

    float4 bv = *(const float4*)(b1 + col0 + c0);
#pragma unroll
    for (int q = 0; q < 4; q++) {
        float4 o;
        o.x = fmaxf(acc[q][0] + bv.x, 0.f); o.y = fmaxf(acc[q][1] + bv.y, 0.f);
        o.z = fmaxf(acc[q][2] + bv.z, 0.f); o.w = fmaxf(acc[q][3] + bv.w, 0.f);
        *(float4*)(g_hid + (r0 + q) * 256 + col0 + c0) = o;
    }
}

// ---------------- K6: logits ----------------
__global__ void __launch_bounds__(512) k6_logits(
    const float* __restrict__ W2, const float* __restrict__ b2,
    float* __restrict__ out)
{
    extern __shared__ float sm[];
    float* hidS = sm;
    float* W2s  = sm + 16384;
    int tid = threadIdx.x;
    for (int i = tid; i < 16384; i += 512) hidS[i] = g_hid[i];
    for (int i = tid; i < 1280; i += 512) W2s[i] = W2[i];
    __syncthreads();
    if (tid < 320) {
        int doc = tid / 5, o = tid % 5;
        float acc = b2[o];
#pragma unroll 8
        for (int k = 0; k < 256; k++)
            acc += hidS[doc * 256 + k] * W2s[k * 5 + o];
        out[doc * 5 + o] = acc;
    }
}

// ---------------- launcher ----------------
extern "C" void kernel_launch(void* const* d_in, const int* in_sizes, int n_in,
                              void* d_out, int out_size)
{
    const int*   X     = (const int*)d_in[0];
    const int*   L     = (const int*)d_in[1];
    const int*   L2    = (const int*)d_in[2];
    const float* emb   = (const float*)d_in[3];
    const float* sWg_f = (const float*)d_in[4];
    const float* sbg_f = (const float*)d_in[5];
    const float* sWc_f = (const float*)d_in[6];
    const float* sbc_f = (const float*)d_in[7];
    const float* sWg_b = (const float*)d_in[8];
    const float* sbg_b = (const float*)d_in[9];
    const float* sWc_b = (const float*)d_in[10];
    const float* sbc_b = (const float*)d_in[11];
    const float* dWg_f = (const float*)d_in[12];
    const float* dbg_f = (const float*)d_in[13];
    const float* dWc_f = (const float*)d_in[14];
    const float* dbc_f = (const float*)d_in[15];
    const float* dWg_b = (const float*)d_in[16];
    const float* dbg_b = (const float*)d_in[17];
    const float* dWc_b = (const float*)d_in[18];
    const float* dbc_b = (const float*)d_in[19];
    const float* W1    = (const float*)d_in[20];
    const float* b1    = (const float*)d_in[21];
    const float* W2    = (const float*)d_in[22];
    const float* b2    = (const float*)d_in[23];
    float* out = (float*)d_out;

    cudaFuncSetAttribute(k1_wordgemm, cudaFuncAttributeMaxDynamicSharedMemorySize, SMEM_K1);
    cudaFuncSetAttribute(k2_sentgru,  cudaFuncAttributeMaxDynamicSharedMemorySize, SMEM_K2);
    cudaFuncSetAttribute(k3_docgemm,  cudaFuncAttributeMaxDynamicSharedMemorySize, SMEM_GEMM);
    cudaFuncSetAttribute(k4_docgru,   cudaFuncAttributeMaxDynamicSharedMemorySize, SMEM_K4);
    cudaFuncSetAttribute(k5_mlp1,     cudaFuncAttributeMaxDynamicSharedMemorySize, SMEM_GEMM);
    cudaFuncSetAttribute(k6_logits,   cudaFuncAttributeMaxDynamicSharedMemorySize, SMEM_K6);

    // split k0 keeps ncu's captured launch on k2_sentgru (verify prefetch delta)
    k0a_sort<<<1, 256>>>(L);
    k0b_sort<<<1, 256>>>(L2);
    dim3 g1(2048, 12);
    k1_wordgemm<<<g1, 256, SMEM_K1>>>(X, L, emb, sWg_f, sbg_f, sWc_f, sbc_f,
                                      sWg_b, sbg_b, sWc_b, sbc_b);
    k2_sentgru<<<256, 512, SMEM_K2>>>(L, sWg_f, sWc_f, sWg_b, sWc_b);
    dim3 g3(32, 24);
    k3_docgemm<<<g3, 256, SMEM_GEMM>>>(dWg_f, dbg_f, dWc_f, dbc_f,
                                       dWg_b, dbg_b, dWc_b, dbc_b);
    k4_docgru<<<64, 512, SMEM_K4>>>(dWg_f, dWc_f, dWg_b, dWc_b, L2);
    k5_mlp1<<<4, 256, SMEM_GEMM>>>(W1, b1);
    k6_logits<<<1, 512, SMEM_K6>>>(W2, b2, out);
}